// round 8
// baseline (speedup 1.0000x reference)
#include <cuda_runtime.h>
#include <cstdint>

#define NN 10000
#define DD 128
#define MAXE 256             // max nonzeros/row (mean ~31, extreme tail ~70)
#define CHUNK4 500           // float4 per chunk  (5 * 500 = 2500 = row)
#define CHUNKB (CHUNK4 * 16) // 8000 bytes
#define NCHUNK 5
#define STAGES 2
#define GRID 1480            // persistent: one wave at ~10 CTAs/SM

__device__ float g_score[NN];

// ---- mbarrier / bulk-async helpers ----------------------------------------
__device__ __forceinline__ uint32_t smem_u32(const void* p) {
    return (uint32_t)__cvta_generic_to_shared(p);
}
__device__ __forceinline__ void mbar_init(uint32_t addr, uint32_t cnt) {
    asm volatile("mbarrier.init.shared.b64 [%0], %1;" :: "r"(addr), "r"(cnt) : "memory");
}
__device__ __forceinline__ void mbar_expect_tx(uint32_t addr, uint32_t bytes) {
    asm volatile("mbarrier.arrive.expect_tx.shared.b64 _, [%0], %1;"
                 :: "r"(addr), "r"(bytes) : "memory");
}
// try_wait with ns-timeout hint: HW-sleep instead of hard spin
__device__ __forceinline__ void mbar_wait(uint32_t addr, uint32_t parity) {
    asm volatile(
        "{\n\t"
        ".reg .pred P;\n\t"
        "LAB_WAIT%=:\n\t"
        "mbarrier.try_wait.parity.shared.b64 P, [%0], %1, 0x989680;\n\t"
        "@P bra LAB_DONE%=;\n\t"
        "bra LAB_WAIT%=;\n\t"
        "LAB_DONE%=:\n\t"
        "}"
        :: "r"(addr), "r"(parity) : "memory");
}
__device__ __forceinline__ void bulk_g2s(uint32_t dst, const void* src,
                                         uint32_t bytes, uint32_t mbar) {
    asm volatile(
        "cp.async.bulk.shared::cluster.global.mbarrier::complete_tx::bytes "
        "[%0], [%1], %2, [%3];"
        :: "r"(dst), "l"(src), "r"(bytes), "r"(mbar) : "memory");
}

// ---------------------------------------------------------------------------
// Kernel 1: score[j] = dot(inputs[j,:], H_v)   — one warp per row
// ---------------------------------------------------------------------------
__global__ __launch_bounds__(128) void score_kernel(
    const float* __restrict__ inputs, const float* __restrict__ Hv)
{
    int row  = blockIdx.x * (blockDim.x >> 5) + (threadIdx.x >> 5);
    int lane = threadIdx.x & 31;
    if (row >= NN) return;
    const float4* ip = reinterpret_cast<const float4*>(inputs + (size_t)row * DD);
    const float4* hv = reinterpret_cast<const float4*>(Hv);
    float4 a = ip[lane];
    float4 h = hv[lane];
    float acc = a.x * h.x + a.y * h.y + a.z * h.z + a.w * h.w;
    #pragma unroll
    for (int off = 16; off > 0; off >>= 1)
        acc += __shfl_xor_sync(0xffffffffu, acc, off);
    if (lane == 0) g_score[row] = acc;
}

// ---------------------------------------------------------------------------
// Kernel 2: persistent CTAs, 128 threads, rows b, b+GRID, ...
// Bulk-async 2-stage ring runs CONTINUOUSLY across row boundaries: while the
// epilogue of row i executes, chunks of row i+1 are already in flight.
// ---------------------------------------------------------------------------
__global__ __launch_bounds__(128) void attn_kernel(
    const float* __restrict__ inputs,
    const float* __restrict__ adj,
    float* __restrict__ out)
{
    __shared__ alignas(16) float4 s_buf[STAGES][CHUNK4];
    __shared__ alignas(16) float  s_w[MAXE];
    __shared__ alignas(16) float  s_part[4 * DD];
    __shared__ int   s_idx[MAXE];
    __shared__ alignas(8) unsigned long long s_bar[STAGES];
    __shared__ int   s_cnt;
    __shared__ float s_red[4];

    const int bid  = blockIdx.x;
    const int tid  = threadIdx.x;
    const int wid  = tid >> 5;
    const int lane = tid & 31;

    const uint32_t barA[STAGES] = { smem_u32(&s_bar[0]), smem_u32(&s_bar[1]) };
    const uint32_t bufA[STAGES] = { smem_u32(&s_buf[0][0]), smem_u32(&s_buf[1][0]) };
    const char* adjB = reinterpret_cast<const char*>(adj);

    const int nrows  = (NN - 1 - bid) / GRID + 1;
    const int totalc = nrows * NCHUNK;

    // global chunk g -> source address
    auto chunk_src = [&](int g) -> const char* {
        int ri = g / NCHUNK, c = g - ri * NCHUNK;
        size_t row = (size_t)(bid + ri * GRID);
        return adjB + row * (NN * 4) + (size_t)c * CHUNKB;
    };

    if (tid == 0) {
        s_cnt = 0;
        mbar_init(barA[0], 1);
        mbar_init(barA[1], 1);
        // prime the ring
        #pragma unroll
        for (int g = 0; g < STAGES; g++) {
            mbar_expect_tx(barA[g], CHUNKB);
            bulk_g2s(bufA[g], chunk_src(g), CHUNKB, barA[g]);
        }
    }
    __syncthreads();

    int g = 0;
    for (int ri = 0; ri < nrows; ri++) {
        const int row = bid + ri * GRID;

        // ---- scan 5 chunks of this row ------------------------------------
        for (int c = 0; c < NCHUNK; c++, g++) {
            const int st = g & (STAGES - 1);
            mbar_wait(barA[st], (g >> 1) & 1);

            const float4* buf = s_buf[st];
            const int jbase = c * (CHUNK4 * 4);
            #pragma unroll
            for (int u = 0; u < 4; u++) {
                const int v = tid + u * 128;
                if (v < CHUNK4) {
                    float4 a = buf[v];
                    int j = jbase + (v << 2);
                    if (a.x != 0.0f) { int p = atomicAdd(&s_cnt, 1); s_idx[p] = j;     s_w[p] = a.x; }
                    if (a.y != 0.0f) { int p = atomicAdd(&s_cnt, 1); s_idx[p] = j + 1; s_w[p] = a.y; }
                    if (a.z != 0.0f) { int p = atomicAdd(&s_cnt, 1); s_idx[p] = j + 2; s_w[p] = a.z; }
                    if (a.w != 0.0f) { int p = atomicAdd(&s_cnt, 1); s_idx[p] = j + 3; s_w[p] = a.w; }
                }
            }
            __syncthreads();                 // stage st fully consumed
            if (tid == 0 && g + STAGES < totalc) {
                mbar_expect_tx(barA[st], CHUNKB);
                bulk_g2s(bufA[st], chunk_src(g + STAGES), CHUNKB, barA[st]);
            }
        }
        const int cnt = s_cnt;

        // ---- epilogue (next row's chunks loading concurrently) -------------
        for (int k = tid; k < cnt; k += 128)
            s_w[k] = s_w[k] * __ldg(&g_score[s_idx[k]]);
        __syncthreads();

        float m = -1e30f;
        for (int k = tid; k < cnt; k += 128) m = fmaxf(m, s_w[k]);
        #pragma unroll
        for (int off = 16; off > 0; off >>= 1)
            m = fmaxf(m, __shfl_xor_sync(0xffffffffu, m, off));
        if (lane == 0) s_red[wid] = m;
        __syncthreads();
        m = fmaxf(fmaxf(s_red[0], s_red[1]), fmaxf(s_red[2], s_red[3]));
        __syncthreads();

        float s = 0.0f;
        for (int k = tid; k < cnt; k += 128) {
            float e = __expf(s_w[k] - m);
            s_w[k] = e;
            s += e;
        }
        #pragma unroll
        for (int off = 16; off > 0; off >>= 1)
            s += __shfl_xor_sync(0xffffffffu, s, off);
        if (lane == 0) s_red[wid] = s;
        __syncthreads();
        s = s_red[0] + s_red[1] + s_red[2] + s_red[3];
        const float inv = 1.0f / s;

        const float4* inp4 = reinterpret_cast<const float4*>(inputs);
        float4 acc = make_float4(0.f, 0.f, 0.f, 0.f);
        int k = wid;
        for (; k + 12 < cnt; k += 16) {
            float w0 = s_w[k],      w1 = s_w[k + 4],  w2 = s_w[k + 8],  w3 = s_w[k + 12];
            int   j0 = s_idx[k],    j1 = s_idx[k + 4], j2 = s_idx[k + 8], j3 = s_idx[k + 12];
            float4 x0 = __ldg(&inp4[(size_t)j0 * 32 + lane]);
            float4 x1 = __ldg(&inp4[(size_t)j1 * 32 + lane]);
            float4 x2 = __ldg(&inp4[(size_t)j2 * 32 + lane]);
            float4 x3 = __ldg(&inp4[(size_t)j3 * 32 + lane]);
            acc.x += w0 * x0.x + w1 * x1.x + w2 * x2.x + w3 * x3.x;
            acc.y += w0 * x0.y + w1 * x1.y + w2 * x2.y + w3 * x3.y;
            acc.z += w0 * x0.z + w1 * x1.z + w2 * x2.z + w3 * x3.z;
            acc.w += w0 * x0.w + w1 * x1.w + w2 * x2.w + w3 * x3.w;
        }
        for (; k < cnt; k += 4) {
            float w0 = s_w[k];
            int   j0 = s_idx[k];
            float4 x0 = __ldg(&inp4[(size_t)j0 * 32 + lane]);
            acc.x += w0 * x0.x; acc.y += w0 * x0.y;
            acc.z += w0 * x0.z; acc.w += w0 * x0.w;
        }
        reinterpret_cast<float4*>(s_part)[wid * 32 + lane] = acc;
        __syncthreads();

        float v = (s_part[tid] + s_part[DD + tid] +
                   s_part[2 * DD + tid] + s_part[3 * DD + tid]) * inv;
        out[(size_t)row * DD + tid] = v;

        __syncthreads();                 // all reads of s_w/s_idx done
        if (tid == 0) s_cnt = 0;
        __syncthreads();                 // next row's scan may start
    }
}

// ---------------------------------------------------------------------------
extern "C" void kernel_launch(void* const* d_in, const int* in_sizes, int n_in,
                              void* d_out, int out_size)
{
    const float* inputs = (const float*)d_in[0];  // [10000,128]
    const float* adj    = (const float*)d_in[1];  // [10000,10000]
    const float* Hv     = (const float*)d_in[2];  // [128,1]
    float* out          = (float*)d_out;          // [10000,128]

    score_kernel<<<(NN + 3) / 4, 128>>>(inputs, Hv);
    attn_kernel<<<GRID, 128>>>(inputs, adj, out);
}

// round 9
// speedup vs baseline: 1.1629x; 1.1629x over previous
#include <cuda_runtime.h>
#include <cstdint>

#define NN 10000
#define DD 128
#define MAXE 256             // max nonzeros/row (mean ~31, extreme tail ~70)
#define CHUNK4 500           // float4 per chunk  (5 * 500 = 2500 = row)
#define CHUNKB (CHUNK4 * 16) // 8000 bytes
#define NCHUNK 5
#define STAGES 2
#define GRID 1480            // persistent: one wave at 10 CTAs/SM

__device__ float g_score[NN];

// ---- mbarrier / bulk-async helpers ----------------------------------------
__device__ __forceinline__ uint32_t smem_u32(const void* p) {
    return (uint32_t)__cvta_generic_to_shared(p);
}
__device__ __forceinline__ void mbar_init(uint32_t addr, uint32_t cnt) {
    asm volatile("mbarrier.init.shared.b64 [%0], %1;" :: "r"(addr), "r"(cnt) : "memory");
}
__device__ __forceinline__ void mbar_expect_tx(uint32_t addr, uint32_t bytes) {
    asm volatile("mbarrier.arrive.expect_tx.shared.b64 _, [%0], %1;"
                 :: "r"(addr), "r"(bytes) : "memory");
}
__device__ __forceinline__ void mbar_wait(uint32_t addr, uint32_t parity) {
    asm volatile(
        "{\n\t"
        ".reg .pred P;\n\t"
        "LAB_WAIT%=:\n\t"
        "mbarrier.try_wait.parity.shared.b64 P, [%0], %1, 0x989680;\n\t"
        "@P bra LAB_DONE%=;\n\t"
        "bra LAB_WAIT%=;\n\t"
        "LAB_DONE%=:\n\t"
        "}"
        :: "r"(addr), "r"(parity) : "memory");
}
__device__ __forceinline__ void bulk_g2s(uint32_t dst, const void* src,
                                         uint32_t bytes, uint32_t mbar) {
    asm volatile(
        "cp.async.bulk.shared::cluster.global.mbarrier::complete_tx::bytes "
        "[%0], [%1], %2, [%3];"
        :: "r"(dst), "l"(src), "r"(bytes), "r"(mbar) : "memory");
}

// ---------------------------------------------------------------------------
// Kernel 1: score[j] = dot(inputs[j,:], H_v)   — one warp per row
// ---------------------------------------------------------------------------
__global__ __launch_bounds__(128) void score_kernel(
    const float* __restrict__ inputs, const float* __restrict__ Hv)
{
    int row  = blockIdx.x * (blockDim.x >> 5) + (threadIdx.x >> 5);
    int lane = threadIdx.x & 31;
    if (row >= NN) return;
    const float4* ip = reinterpret_cast<const float4*>(inputs + (size_t)row * DD);
    const float4* hv = reinterpret_cast<const float4*>(Hv);
    float4 a = ip[lane];
    float4 h = hv[lane];
    float acc = a.x * h.x + a.y * h.y + a.z * h.z + a.w * h.w;
    #pragma unroll
    for (int off = 16; off > 0; off >>= 1)
        acc += __shfl_xor_sync(0xffffffffu, acc, off);
    if (lane == 0) g_score[row] = acc;
}

// ---------------------------------------------------------------------------
// Kernel 2: persistent CTAs (10/SM enforced), 128 threads, rows b, b+GRID, ...
// Bulk-async 2-stage ring runs continuously across row boundaries.
// Thread 0 maintains the next-chunk src pointer INCREMENTALLY (no div/mul).
// ---------------------------------------------------------------------------
__global__ __launch_bounds__(128, 10) void attn_kernel(
    const float* __restrict__ inputs,
    const float* __restrict__ adj,
    float* __restrict__ out)
{
    __shared__ alignas(16) float4 s_buf[STAGES][CHUNK4];
    __shared__ alignas(16) float  s_w[MAXE];
    __shared__ alignas(16) float  s_part[4 * DD];
    __shared__ int   s_idx[MAXE];
    __shared__ alignas(8) unsigned long long s_bar[STAGES];
    __shared__ int   s_cnt;
    __shared__ float s_red[4];

    const int bid  = blockIdx.x;
    const int tid  = threadIdx.x;
    const int wid  = tid >> 5;
    const int lane = tid & 31;

    const uint32_t barA[STAGES] = { smem_u32(&s_bar[0]), smem_u32(&s_bar[1]) };
    const uint32_t bufA[STAGES] = { smem_u32(&s_buf[0][0]), smem_u32(&s_buf[1][0]) };

    const int nrows  = (NN - 1 - bid) / GRID + 1;
    const int totalc = nrows * NCHUNK;

    // thread-0 incremental prefetch state (registers; no division anywhere)
    const char* nsrc = reinterpret_cast<const char*>(adj) + (size_t)bid * (NN * 4);
    int nc = 0;          // chunk index within current prefetch row
    int ng = 0;          // global chunk counter of next issue

    if (tid == 0) {
        s_cnt = 0;
        mbar_init(barA[0], 1);
        mbar_init(barA[1], 1);
        // prime the ring (chunks 0,1 — same row, nrows*NCHUNK >= 5 > 2)
        #pragma unroll
        for (int st = 0; st < STAGES; st++) {
            mbar_expect_tx(barA[st], CHUNKB);
            bulk_g2s(bufA[st], nsrc, CHUNKB, barA[st]);
            nsrc += CHUNKB; nc++; ng++;
            if (nc == NCHUNK) { nc = 0; nsrc += (size_t)(GRID - 1) * (NN * 4); }
        }
    }
    __syncthreads();

    int g = 0;
    for (int ri = 0; ri < nrows; ri++) {
        const int row = bid + ri * GRID;

        // ---- scan 5 chunks of this row ------------------------------------
        for (int c = 0; c < NCHUNK; c++, g++) {
            const int st = g & (STAGES - 1);
            mbar_wait(barA[st], (g >> 1) & 1);

            const float4* buf = s_buf[st];
            const int jbase = c * (CHUNK4 * 4);
            #pragma unroll
            for (int u = 0; u < 4; u++) {
                const int v = tid + u * 128;
                if (v < CHUNK4) {
                    float4 a = buf[v];
                    int j = jbase + (v << 2);
                    if (a.x != 0.0f) { int p = atomicAdd(&s_cnt, 1); s_idx[p] = j;     s_w[p] = a.x; }
                    if (a.y != 0.0f) { int p = atomicAdd(&s_cnt, 1); s_idx[p] = j + 1; s_w[p] = a.y; }
                    if (a.z != 0.0f) { int p = atomicAdd(&s_cnt, 1); s_idx[p] = j + 2; s_w[p] = a.z; }
                    if (a.w != 0.0f) { int p = atomicAdd(&s_cnt, 1); s_idx[p] = j + 3; s_w[p] = a.w; }
                }
            }
            __syncthreads();                 // stage st fully consumed
            if (tid == 0 && ng < totalc) {   // refill stage st with next chunk
                mbar_expect_tx(barA[st], CHUNKB);
                bulk_g2s(bufA[st], nsrc, CHUNKB, barA[st]);
                nsrc += CHUNKB; nc++; ng++;
                if (nc == NCHUNK) { nc = 0; nsrc += (size_t)(GRID - 1) * (NN * 4); }
            }
        }
        const int cnt = s_cnt;

        // ---- epilogue (next row's chunks loading concurrently) -------------
        for (int k = tid; k < cnt; k += 128)
            s_w[k] = s_w[k] * __ldg(&g_score[s_idx[k]]);
        __syncthreads();

        float m = -1e30f;
        for (int k = tid; k < cnt; k += 128) m = fmaxf(m, s_w[k]);
        #pragma unroll
        for (int off = 16; off > 0; off >>= 1)
            m = fmaxf(m, __shfl_xor_sync(0xffffffffu, m, off));
        if (lane == 0) s_red[wid] = m;
        __syncthreads();
        m = fmaxf(fmaxf(s_red[0], s_red[1]), fmaxf(s_red[2], s_red[3]));
        __syncthreads();

        float s = 0.0f;
        for (int k = tid; k < cnt; k += 128) {
            float e = __expf(s_w[k] - m);
            s_w[k] = e;
            s += e;
        }
        #pragma unroll
        for (int off = 16; off > 0; off >>= 1)
            s += __shfl_xor_sync(0xffffffffu, s, off);
        if (lane == 0) s_red[wid] = s;
        __syncthreads();
        s = s_red[0] + s_red[1] + s_red[2] + s_red[3];
        const float inv = 1.0f / s;

        const float4* inp4 = reinterpret_cast<const float4*>(inputs);
        float4 acc = make_float4(0.f, 0.f, 0.f, 0.f);
        int k = wid;
        for (; k + 12 < cnt; k += 16) {
            float w0 = s_w[k],      w1 = s_w[k + 4],  w2 = s_w[k + 8],  w3 = s_w[k + 12];
            int   j0 = s_idx[k],    j1 = s_idx[k + 4], j2 = s_idx[k + 8], j3 = s_idx[k + 12];
            float4 x0 = __ldg(&inp4[(size_t)j0 * 32 + lane]);
            float4 x1 = __ldg(&inp4[(size_t)j1 * 32 + lane]);
            float4 x2 = __ldg(&inp4[(size_t)j2 * 32 + lane]);
            float4 x3 = __ldg(&inp4[(size_t)j3 * 32 + lane]);
            acc.x += w0 * x0.x + w1 * x1.x + w2 * x2.x + w3 * x3.x;
            acc.y += w0 * x0.y + w1 * x1.y + w2 * x2.y + w3 * x3.y;
            acc.z += w0 * x0.z + w1 * x1.z + w2 * x2.z + w3 * x3.z;
            acc.w += w0 * x0.w + w1 * x1.w + w2 * x2.w + w3 * x3.w;
        }
        for (; k < cnt; k += 4) {
            float w0 = s_w[k];
            int   j0 = s_idx[k];
            float4 x0 = __ldg(&inp4[(size_t)j0 * 32 + lane]);
            acc.x += w0 * x0.x; acc.y += w0 * x0.y;
            acc.z += w0 * x0.z; acc.w += w0 * x0.w;
        }
        reinterpret_cast<float4*>(s_part)[wid * 32 + lane] = acc;
        __syncthreads();

        float v = (s_part[tid] + s_part[DD + tid] +
                   s_part[2 * DD + tid] + s_part[3 * DD + tid]) * inv;
        out[(size_t)row * DD + tid] = v;

        __syncthreads();                 // all reads of s_w/s_idx done
        if (tid == 0) s_cnt = 0;
        __syncthreads();                 // next row's scan may start
    }
}

// ---------------------------------------------------------------------------
extern "C" void kernel_launch(void* const* d_in, const int* in_sizes, int n_in,
                              void* d_out, int out_size)
{
    const float* inputs = (const float*)d_in[0];  // [10000,128]
    const float* adj    = (const float*)d_in[1];  // [10000,10000]
    const float* Hv     = (const float*)d_in[2];  // [128,1]
    float* out          = (float*)d_out;          // [10000,128]

    score_kernel<<<(NN + 3) / 4, 128>>>(inputs, Hv);
    attn_kernel<<<GRID, 128>>>(inputs, adj, out);
}

// round 10
// speedup vs baseline: 1.4014x; 1.2051x over previous
#include <cuda_runtime.h>
#include <cstdint>

#define NN 10000
#define DD 128
#define MAXE 256             // max nonzeros/row (mean ~31, extreme tail ~70)
#define CHUNK4 250           // float4 per chunk (10 * 250 = 2500 = row)
#define CHUNKB (CHUNK4 * 16) // 4000 bytes
#define NCHUNK 10
#define STAGES 4

__device__ float g_score[NN];

// ---- mbarrier / bulk-async helpers ----------------------------------------
__device__ __forceinline__ uint32_t smem_u32(const void* p) {
    return (uint32_t)__cvta_generic_to_shared(p);
}
__device__ __forceinline__ void mbar_init(uint32_t addr, uint32_t cnt) {
    asm volatile("mbarrier.init.shared.b64 [%0], %1;" :: "r"(addr), "r"(cnt) : "memory");
}
__device__ __forceinline__ void mbar_expect_tx(uint32_t addr, uint32_t bytes) {
    asm volatile("mbarrier.arrive.expect_tx.shared.b64 _, [%0], %1;"
                 :: "r"(addr), "r"(bytes) : "memory");
}
__device__ __forceinline__ void mbar_wait(uint32_t addr, uint32_t parity) {
    asm volatile(
        "{\n\t"
        ".reg .pred P;\n\t"
        "LAB_WAIT%=:\n\t"
        "mbarrier.try_wait.parity.shared.b64 P, [%0], %1, 0x989680;\n\t"
        "@P bra LAB_DONE%=;\n\t"
        "bra LAB_WAIT%=;\n\t"
        "LAB_DONE%=:\n\t"
        "}"
        :: "r"(addr), "r"(parity) : "memory");
}
__device__ __forceinline__ void bulk_g2s(uint32_t dst, const void* src,
                                         uint32_t bytes, uint32_t mbar) {
    asm volatile(
        "cp.async.bulk.shared::cluster.global.mbarrier::complete_tx::bytes "
        "[%0], [%1], %2, [%3];"
        :: "r"(dst), "l"(src), "r"(bytes), "r"(mbar) : "memory");
}

// ---------------------------------------------------------------------------
// Kernel 1: score[j] = dot(inputs[j,:], H_v)   — one warp per row
// ---------------------------------------------------------------------------
__global__ __launch_bounds__(128) void score_kernel(
    const float* __restrict__ inputs, const float* __restrict__ Hv)
{
    int row  = blockIdx.x * (blockDim.x >> 5) + (threadIdx.x >> 5);
    int lane = threadIdx.x & 31;
    if (row >= NN) return;
    const float4* ip = reinterpret_cast<const float4*>(inputs + (size_t)row * DD);
    const float4* hv = reinterpret_cast<const float4*>(Hv);
    float4 a = ip[lane];
    float4 h = hv[lane];
    float acc = a.x * h.x + a.y * h.y + a.z * h.z + a.w * h.w;
    #pragma unroll
    for (int off = 16; off > 0; off >>= 1)
        acc += __shfl_xor_sync(0xffffffffu, acc, off);
    if (lane == 0) g_score[row] = acc;
}

// ---------------------------------------------------------------------------
// Kernel 2: one CTA per row (non-persistent — HW CTA replacement is the best
// prefetcher). 4-stage x 4KB bulk-async ring for deeper engine occupancy.
// ---------------------------------------------------------------------------
__global__ __launch_bounds__(128, 11) void attn_kernel(
    const float* __restrict__ inputs,
    const float* __restrict__ adj,
    float* __restrict__ out)
{
    __shared__ alignas(16) float4 s_buf[STAGES][CHUNK4];
    __shared__ alignas(16) float  s_w[MAXE];
    __shared__ alignas(16) float  s_part[4 * DD];
    __shared__ int   s_idx[MAXE];
    __shared__ alignas(8) unsigned long long s_bar[STAGES];
    __shared__ int   s_cnt;
    __shared__ float s_red[4];

    const int row  = blockIdx.x;
    const int tid  = threadIdx.x;
    const int wid  = tid >> 5;
    const int lane = tid & 31;

    const char* arow = reinterpret_cast<const char*>(adj) + (size_t)row * (NN * 4);

    if (tid == 0) {
        s_cnt = 0;
        #pragma unroll
        for (int st = 0; st < STAGES; st++) mbar_init(smem_u32(&s_bar[st]), 1);
    }
    __syncthreads();

    // Prime all 4 stages
    if (tid == 0) {
        #pragma unroll
        for (int st = 0; st < STAGES; st++) {
            mbar_expect_tx(smem_u32(&s_bar[st]), CHUNKB);
            bulk_g2s(smem_u32(&s_buf[st][0]), arow + (size_t)st * CHUNKB,
                     CHUNKB, smem_u32(&s_bar[st]));
        }
    }

    // ---- Pass 1: chunked scan from SMEM ------------------------------------
    for (int c = 0; c < NCHUNK; c++) {
        const int st = c & (STAGES - 1);
        mbar_wait(smem_u32(&s_bar[st]), (c >> 2) & 1);

        const float4* buf = s_buf[st];
        const int jbase = c * (CHUNK4 * 4);
        #pragma unroll
        for (int u = 0; u < 2; u++) {
            const int v = tid + u * 128;
            if (v < CHUNK4) {
                float4 a = buf[v];
                int j = jbase + (v << 2);
                if (a.x != 0.0f) { int p = atomicAdd(&s_cnt, 1); s_idx[p] = j;     s_w[p] = a.x; }
                if (a.y != 0.0f) { int p = atomicAdd(&s_cnt, 1); s_idx[p] = j + 1; s_w[p] = a.y; }
                if (a.z != 0.0f) { int p = atomicAdd(&s_cnt, 1); s_idx[p] = j + 2; s_w[p] = a.z; }
                if (a.w != 0.0f) { int p = atomicAdd(&s_cnt, 1); s_idx[p] = j + 3; s_w[p] = a.w; }
            }
        }
        __syncthreads();                     // stage st fully consumed
        if (tid == 0 && c + STAGES < NCHUNK) {
            mbar_expect_tx(smem_u32(&s_bar[st]), CHUNKB);
            bulk_g2s(smem_u32(&s_buf[st][0]),
                     arow + (size_t)(c + STAGES) * CHUNKB,
                     CHUNKB, smem_u32(&s_bar[st]));
        }
    }
    const int cnt = s_cnt;

    // ---- Pass 2a: logits (parallel score gather) ---------------------------
    for (int k = tid; k < cnt; k += 128)
        s_w[k] = s_w[k] * __ldg(&g_score[s_idx[k]]);
    __syncthreads();

    // ---- Pass 2b: softmax --------------------------------------------------
    float m = -1e30f;
    for (int k = tid; k < cnt; k += 128) m = fmaxf(m, s_w[k]);
    #pragma unroll
    for (int off = 16; off > 0; off >>= 1)
        m = fmaxf(m, __shfl_xor_sync(0xffffffffu, m, off));
    if (lane == 0) s_red[wid] = m;
    __syncthreads();
    m = fmaxf(fmaxf(s_red[0], s_red[1]), fmaxf(s_red[2], s_red[3]));
    __syncthreads();

    float s = 0.0f;
    for (int k = tid; k < cnt; k += 128) {
        float e = __expf(s_w[k] - m);
        s_w[k] = e;
        s += e;
    }
    #pragma unroll
    for (int off = 16; off > 0; off >>= 1)
        s += __shfl_xor_sync(0xffffffffu, s, off);
    if (lane == 0) s_red[wid] = s;
    __syncthreads();
    s = s_red[0] + s_red[1] + s_red[2] + s_red[3];
    const float inv = 1.0f / s;

    // ---- Pass 3: warp-split float4 gather ----------------------------------
    const float4* inp4 = reinterpret_cast<const float4*>(inputs);
    float4 acc = make_float4(0.f, 0.f, 0.f, 0.f);
    int k = wid;
    for (; k + 12 < cnt; k += 16) {
        float w0 = s_w[k],      w1 = s_w[k + 4],  w2 = s_w[k + 8],  w3 = s_w[k + 12];
        int   j0 = s_idx[k],    j1 = s_idx[k + 4], j2 = s_idx[k + 8], j3 = s_idx[k + 12];
        float4 x0 = __ldg(&inp4[(size_t)j0 * 32 + lane]);
        float4 x1 = __ldg(&inp4[(size_t)j1 * 32 + lane]);
        float4 x2 = __ldg(&inp4[(size_t)j2 * 32 + lane]);
        float4 x3 = __ldg(&inp4[(size_t)j3 * 32 + lane]);
        acc.x += w0 * x0.x + w1 * x1.x + w2 * x2.x + w3 * x3.x;
        acc.y += w0 * x0.y + w1 * x1.y + w2 * x2.y + w3 * x3.y;
        acc.z += w0 * x0.z + w1 * x1.z + w2 * x2.z + w3 * x3.z;
        acc.w += w0 * x0.w + w1 * x1.w + w2 * x2.w + w3 * x3.w;
    }
    for (; k < cnt; k += 4) {
        float w0 = s_w[k];
        int   j0 = s_idx[k];
        float4 x0 = __ldg(&inp4[(size_t)j0 * 32 + lane]);
        acc.x += w0 * x0.x; acc.y += w0 * x0.y;
        acc.z += w0 * x0.z; acc.w += w0 * x0.w;
    }
    reinterpret_cast<float4*>(s_part)[wid * 32 + lane] = acc;
    __syncthreads();

    float v = (s_part[tid] + s_part[DD + tid] +
               s_part[2 * DD + tid] + s_part[3 * DD + tid]) * inv;
    out[(size_t)row * DD + tid] = v;
}

// ---------------------------------------------------------------------------
extern "C" void kernel_launch(void* const* d_in, const int* in_sizes, int n_in,
                              void* d_out, int out_size)
{
    const float* inputs = (const float*)d_in[0];  // [10000,128]
    const float* adj    = (const float*)d_in[1];  // [10000,10000]
    const float* Hv     = (const float*)d_in[2];  // [128,1]
    float* out          = (float*)d_out;          // [10000,128]

    score_kernel<<<(NN + 3) / 4, 128>>>(inputs, Hv);
    attn_kernel<<<NN, 128>>>(inputs, adj, out);
}